// round 15
// baseline (speedup 1.0000x reference)
#include <cuda_runtime.h>
#include <cuda_fp16.h>

#define N_USERS 100000
#define N_ITEMS 200000
#define N_NODES (N_USERS + N_ITEMS)
#define NNZ 6400000
#define H2_PER_NODE 32                      // 64 dims = 32 half2
#define U2_PER_NODE 16                      // 64 dims = 16 uint2 (4 half each)
#define F4_PER_NODE 16                      // 64 dims = 16 float4
#define BUF_H2 (N_NODES * H2_PER_NODE)      // 9.6M half2 = 38.4 MB
#define SCAN_BLK 1024
#define N_SCAN_BLOCKS ((N_NODES + SCAN_BLK - 1) / SCAN_BLK)   // 293

// Static device scratch. g_x[0]=x0, [1]=x1, [2]=x2 (fp16). x3 never stored.
__device__ __align__(128) __half2 g_x[3][BUF_H2];   // 3 x 38.4 MB
__device__ float2  g_cv[NNZ + 1];            // packed {col_bits, val} (+1 pad)
__device__ int     g_rowptr[N_NODES + 1];
__device__ int     g_cursor[N_NODES];
__device__ int     g_deg[N_NODES];
__device__ int     g_bsum[SCAN_BLK];

// ---- L2 evict_last gather via createpolicy + cache_hint (any width) ----
__device__ __forceinline__ unsigned long long mk_evict_last_policy() {
    unsigned long long pol;
    asm("createpolicy.fractional.L2::evict_last.b64 %0, 1.0;" : "=l"(pol));
    return pol;
}
__device__ __forceinline__ uint2 ldg_evict_last_u2(const uint2* p,
                                                   unsigned long long pol) {
    uint2 r;
    asm volatile("ld.global.nc.L2::cache_hint.v2.u32 {%0,%1}, [%2], %3;"
                 : "=r"(r.x), "=r"(r.y) : "l"(p), "l"(pol));
    return r;
}

// ------------- fused init + histogram (fire-and-forget atomics) -------------
__global__ void init_hist_kernel(const float2* __restrict__ user,
                                 const float2* __restrict__ item,
                                 const int* __restrict__ rows) {
    int i = blockIdx.x * blockDim.x + threadIdx.x;
    if (i < BUF_H2) {
        const int uend = N_USERS * H2_PER_NODE;
        float2 v = (i < uend) ? user[i] : item[i - uend];
        g_x[0][i] = __float22half2_rn(v);
    }
    if (i < NNZ) {
        atomicAdd(&g_deg[rows[i]], 1);
    }
}

// ------------- scan1: per-block exclusive scan, block sums to g_bsum -------------
__global__ void scan1_kernel() {
    __shared__ int s[SCAN_BLK];
    int t = threadIdx.x;
    int i = blockIdx.x * SCAN_BLK + t;
    int v = (i < N_NODES) ? g_deg[i] : 0;
    s[t] = v;
    __syncthreads();
    for (int off = 1; off < SCAN_BLK; off <<= 1) {
        int add = (t >= off) ? s[t - off] : 0;
        __syncthreads();
        s[t] += add;
        __syncthreads();
    }
    int incl = s[t];
    if (i < N_NODES) g_rowptr[i] = incl - v;
    if (t == SCAN_BLK - 1) g_bsum[blockIdx.x] = incl;
}

// ------------- scan23: each block computes its own bsum prefix + applies -------------
__global__ void scan23_kernel() {
    __shared__ int s_off;
    int bid = blockIdx.x;
    int t = threadIdx.x;
    if (t < 32) {
        int acc = 0;
        for (int j = t; j < bid; j += 32) acc += g_bsum[j];
        #pragma unroll
        for (int o = 16; o; o >>= 1) acc += __shfl_xor_sync(0xffffffffu, acc, o);
        if (t == 0) s_off = acc;
    }
    __syncthreads();
    int i = bid * SCAN_BLK + t;
    if (i < N_NODES) {
        int rp = g_rowptr[i] + s_off;
        g_rowptr[i] = rp;
        g_cursor[i] = rp;
        if (i == 0) g_rowptr[N_NODES] = NNZ;
    }
}

// ------------- scatter: 4 edges/thread, 4 independent atomic+store chains -------------
__global__ void scatter_kernel(const int4* __restrict__ rows4,
                               const int4* __restrict__ cols4,
                               const float4* __restrict__ vals4) {
    int i = blockIdx.x * blockDim.x + threadIdx.x;
    if (i >= NNZ / 4) return;
    int4   r = __ldcs(&rows4[i]);
    int4   c = __ldcs(&cols4[i]);
    float4 v = __ldcs(&vals4[i]);

    int p0 = atomicAdd(&g_cursor[r.x], 1);
    int p1 = atomicAdd(&g_cursor[r.y], 1);
    int p2 = atomicAdd(&g_cursor[r.z], 1);
    int p3 = atomicAdd(&g_cursor[r.w], 1);

    __stcs(&g_cv[p0], make_float2(__int_as_float(c.x), v.x));
    __stcs(&g_cv[p1], make_float2(__int_as_float(c.y), v.y));
    __stcs(&g_cv[p2], make_float2(__int_as_float(c.z), v.z));
    __stcs(&g_cv[p3], make_float2(__int_as_float(c.w), v.w));
}

// ---------------- CSR SpMM: warp per row, 16 lanes x uint2, 2 edges/step ------
// x gathers: L2 evict_last (persist). cv: evict_first. y stores: evict_first.
// MODE 0: y[row] = fp16(sum)                                (layers 1,2)
// MODE 1: out[row] = (x0_fp32 + x1 + x2 + sum) * 0.25       (layer 3, fused final)
template <int MODE>
__global__ void spmm_csr_kernel(int srcsel, int dstsel,
                                const float4* __restrict__ user4,
                                const float4* __restrict__ item4,
                                float4* __restrict__ out4) {
    int gtid = blockIdx.x * blockDim.x + threadIdx.x;
    int row = gtid >> 5;
    int lane = threadIdx.x & 31;
    if (row >= N_NODES) return;

    int half = lane >> 4;       // 0 or 1
    int hl   = lane & 15;       // lane within half-warp

    const uint2* __restrict__ x = (const uint2*)g_x[srcsel];
    const unsigned long long pol = mk_evict_last_policy();

    int start = __ldg(&g_rowptr[row]);
    int end   = __ldg(&g_rowptr[row + 1]);

    float4 acc = make_float4(0.f, 0.f, 0.f, 0.f);

    for (int k = start; k < end; k += 32) {
        int myk = k + lane;
        // zero-fill => col 0, val 0: contributes nothing, loads stay valid
        float2 cv = (myk < end) ? __ldcs(&g_cv[myk]) : make_float2(0.f, 0.f);
        int cnt  = min(32, end - k);
        int jmax = (cnt + 1) >> 1;          // uniform across warp

        #pragma unroll 8
        for (int j = 0; j < jmax; j++) {
            int e = 2 * j + half;           // this half-warp's edge slot
            int   cj = __shfl_sync(0xffffffffu, __float_as_int(cv.x), e);
            float vj = __shfl_sync(0xffffffffu, cv.y, e);
            uint2 xr = ldg_evict_last_u2(&x[cj * U2_PER_NODE + hl], pol);
            float2 a = __half22float2(*(const __half2*)&xr.x);
            float2 b = __half22float2(*(const __half2*)&xr.y);
            acc.x = fmaf(vj, a.x, acc.x);
            acc.y = fmaf(vj, a.y, acc.y);
            acc.z = fmaf(vj, b.x, acc.z);
            acc.w = fmaf(vj, b.y, acc.w);
        }
    }

    // combine the two half-warps' partial sums (same dims, different edges)
    acc.x += __shfl_xor_sync(0xffffffffu, acc.x, 16);
    acc.y += __shfl_xor_sync(0xffffffffu, acc.y, 16);
    acc.z += __shfl_xor_sync(0xffffffffu, acc.z, 16);
    acc.w += __shfl_xor_sync(0xffffffffu, acc.w, 16);

    if (half == 0) {
        if (MODE == 0) {
            uint2 o;
            __half2 lo = __float22half2_rn(make_float2(acc.x, acc.y));
            __half2 hi = __float22half2_rn(make_float2(acc.z, acc.w));
            o.x = *(const unsigned int*)&lo;
            o.y = *(const unsigned int*)&hi;
            __stcs(&((uint2*)g_x[dstsel])[row * U2_PER_NODE + hl], o);
        } else {
            int fi = row * F4_PER_NODE + hl;
            float4 x0 = (row < N_USERS)
                      ? __ldg(&user4[fi])
                      : __ldg(&item4[fi - N_USERS * F4_PER_NODE]);
            uint2 r1 = __ldg(&((const uint2*)g_x[1])[row * U2_PER_NODE + hl]);
            uint2 r2 = __ldg(&((const uint2*)g_x[2])[row * U2_PER_NODE + hl]);
            float2 a1 = __half22float2(*(const __half2*)&r1.x);
            float2 b1 = __half22float2(*(const __half2*)&r1.y);
            float2 a2 = __half22float2(*(const __half2*)&r2.x);
            float2 b2 = __half22float2(*(const __half2*)&r2.y);
            float4 o;
            o.x = (x0.x + a1.x + a2.x + acc.x) * 0.25f;
            o.y = (x0.y + a1.y + a2.y + acc.y) * 0.25f;
            o.z = (x0.z + b1.x + b2.x + acc.z) * 0.25f;
            o.w = (x0.w + b1.y + b2.y + acc.w) * 0.25f;
            __stcs(&out4[fi], o);
        }
    }
}

extern "C" void kernel_launch(void* const* d_in, const int* in_sizes, int n_in,
                              void* d_out, int out_size) {
    const float2* user = (const float2*)d_in[0];
    const float2* item = (const float2*)d_in[1];
    const int*   rows  = (const int*)d_in[2];
    const int4*  rows4 = (const int4*)d_in[2];
    const int4*  cols4 = (const int4*)d_in[3];
    const float4* vals4 = (const float4*)d_in[4];
    const float4* user4 = (const float4*)d_in[0];
    const float4* item4 = (const float4*)d_in[1];
    float4* out4 = (float4*)d_out;

    const int BLK = 256;
    const int gridBuf   = (BUF_H2 + BLK - 1) / BLK;         // covers init & hist
    const int gridEdge4 = (NNZ / 4 + BLK - 1) / BLK;
    const int gridSpmm  = (N_NODES * 32 + BLK - 1) / BLK;   // warp per row

    // CSR build + x0 init
    int* d_deg = nullptr;
    cudaGetSymbolAddress((void**)&d_deg, g_deg);
    cudaMemsetAsync(d_deg, 0, N_NODES * sizeof(int));
    init_hist_kernel<<<gridBuf, BLK>>>(user, item, rows);
    scan1_kernel<<<N_SCAN_BLOCKS, SCAN_BLK>>>();
    scan23_kernel<<<N_SCAN_BLOCKS, SCAN_BLK>>>();
    scatter_kernel<<<gridEdge4, BLK>>>(rows4, cols4, vals4);

    // 3 propagation layers; layer 3 fuses the final average + fp32 output
    spmm_csr_kernel<0><<<gridSpmm, BLK>>>(0, 1, user4, item4, out4); // x1 = A@x0
    spmm_csr_kernel<0><<<gridSpmm, BLK>>>(1, 2, user4, item4, out4); // x2 = A@x1
    spmm_csr_kernel<1><<<gridSpmm, BLK>>>(2, 0, user4, item4, out4); // out=(x0+x1+x2+A@x2)/4
}

// round 16
// speedup vs baseline: 1.3339x; 1.3339x over previous
#include <cuda_runtime.h>
#include <cuda_fp16.h>

#define N_USERS 100000
#define N_ITEMS 200000
#define N_NODES (N_USERS + N_ITEMS)
#define NNZ 6400000
#define H2_PER_NODE 32                      // 64 dims = 32 half2
#define U2_PER_NODE 16                      // 64 dims = 16 uint2 (4 half each)
#define F4_PER_NODE 16                      // 64 dims = 16 float4
#define BUF_H2 (N_NODES * H2_PER_NODE)      // 9.6M half2 = 38.4 MB
#define SCAN_BLK 1024
#define N_SCAN_BLOCKS ((N_NODES + SCAN_BLK - 1) / SCAN_BLK)   // 293

// Static device scratch. g_x[0]=x0, [1]=x1, [2]=x2 (fp16). x3 never stored.
__device__ __align__(128) __half2 g_x[3][BUF_H2];   // 3 x 38.4 MB
__device__ float2  g_cv[NNZ + 1];            // packed {col_bits, val} (+1 pad)
__device__ int     g_rowptr[N_NODES + 1];
__device__ int     g_cursor[N_NODES];
__device__ int     g_deg[N_NODES];
__device__ int     g_bsum[SCAN_BLK];

// ------------- fused init + histogram (fire-and-forget atomics) -------------
__global__ void init_hist_kernel(const float2* __restrict__ user,
                                 const float2* __restrict__ item,
                                 const int* __restrict__ rows) {
    int i = blockIdx.x * blockDim.x + threadIdx.x;
    if (i < BUF_H2) {
        const int uend = N_USERS * H2_PER_NODE;
        float2 v = (i < uend) ? user[i] : item[i - uend];
        g_x[0][i] = __float22half2_rn(v);
    }
    if (i < NNZ) {
        atomicAdd(&g_deg[rows[i]], 1);
    }
}

// ------------- scan1: per-block exclusive scan, block sums to g_bsum -------------
__global__ void scan1_kernel() {
    __shared__ int s[SCAN_BLK];
    int t = threadIdx.x;
    int i = blockIdx.x * SCAN_BLK + t;
    int v = (i < N_NODES) ? g_deg[i] : 0;
    s[t] = v;
    __syncthreads();
    for (int off = 1; off < SCAN_BLK; off <<= 1) {
        int add = (t >= off) ? s[t - off] : 0;
        __syncthreads();
        s[t] += add;
        __syncthreads();
    }
    int incl = s[t];
    if (i < N_NODES) g_rowptr[i] = incl - v;
    if (t == SCAN_BLK - 1) g_bsum[blockIdx.x] = incl;
}

// ------------- scan23: each block computes its own bsum prefix + applies -------------
__global__ void scan23_kernel() {
    __shared__ int s_off;
    int bid = blockIdx.x;
    int t = threadIdx.x;
    if (t < 32) {
        int acc = 0;
        for (int j = t; j < bid; j += 32) acc += g_bsum[j];
        #pragma unroll
        for (int o = 16; o; o >>= 1) acc += __shfl_xor_sync(0xffffffffu, acc, o);
        if (t == 0) s_off = acc;
    }
    __syncthreads();
    int i = bid * SCAN_BLK + t;
    if (i < N_NODES) {
        int rp = g_rowptr[i] + s_off;
        g_rowptr[i] = rp;
        g_cursor[i] = rp;
        if (i == 0) g_rowptr[N_NODES] = NNZ;
    }
}

// ------------- scatter: 8 edges/thread, 8 independent atomic+store chains -------------
// cv stores use default policy so the 51 MB cv buffer stays L2-resident for layer 1.
__global__ void scatter_kernel(const int4* __restrict__ rows4,
                               const int4* __restrict__ cols4,
                               const float4* __restrict__ vals4) {
    int i = blockIdx.x * blockDim.x + threadIdx.x;
    if (i >= NNZ / 8) return;
    int base = i * 2;

    int4   r0 = __ldcs(&rows4[base]);
    int4   r1 = __ldcs(&rows4[base + 1]);
    int4   c0 = __ldcs(&cols4[base]);
    int4   c1 = __ldcs(&cols4[base + 1]);
    float4 v0 = __ldcs(&vals4[base]);
    float4 v1 = __ldcs(&vals4[base + 1]);

    int p0 = atomicAdd(&g_cursor[r0.x], 1);
    int p1 = atomicAdd(&g_cursor[r0.y], 1);
    int p2 = atomicAdd(&g_cursor[r0.z], 1);
    int p3 = atomicAdd(&g_cursor[r0.w], 1);
    int p4 = atomicAdd(&g_cursor[r1.x], 1);
    int p5 = atomicAdd(&g_cursor[r1.y], 1);
    int p6 = atomicAdd(&g_cursor[r1.z], 1);
    int p7 = atomicAdd(&g_cursor[r1.w], 1);

    g_cv[p0] = make_float2(__int_as_float(c0.x), v0.x);
    g_cv[p1] = make_float2(__int_as_float(c0.y), v0.y);
    g_cv[p2] = make_float2(__int_as_float(c0.z), v0.z);
    g_cv[p3] = make_float2(__int_as_float(c0.w), v0.w);
    g_cv[p4] = make_float2(__int_as_float(c1.x), v1.x);
    g_cv[p5] = make_float2(__int_as_float(c1.y), v1.y);
    g_cv[p6] = make_float2(__int_as_float(c1.z), v1.z);
    g_cv[p7] = make_float2(__int_as_float(c1.w), v1.w);
}

// ---------------- CSR SpMM: warp per row, 16 lanes x uint2, 2 edges/step ------
// MODE 0: y[row] = fp16(sum)                                (layers 1,2)
// MODE 1: out[row] = (x0_fp32 + x1 + x2 + sum) * 0.25       (layer 3, fused final)
template <int MODE>
__global__ void spmm_csr_kernel(int srcsel, int dstsel,
                                const float4* __restrict__ user4,
                                const float4* __restrict__ item4,
                                float4* __restrict__ out4) {
    int gtid = blockIdx.x * blockDim.x + threadIdx.x;
    int row = gtid >> 5;
    int lane = threadIdx.x & 31;
    if (row >= N_NODES) return;

    int half = lane >> 4;       // 0 or 1
    int hl   = lane & 15;       // lane within half-warp

    const uint2* __restrict__ x = (const uint2*)g_x[srcsel];

    int start = __ldg(&g_rowptr[row]);
    int end   = __ldg(&g_rowptr[row + 1]);

    float4 acc = make_float4(0.f, 0.f, 0.f, 0.f);

    for (int k = start; k < end; k += 32) {
        int myk = k + lane;
        // zero-fill => col 0, val 0: contributes nothing, loads stay valid
        float2 cv = (myk < end) ? __ldcs(&g_cv[myk]) : make_float2(0.f, 0.f);
        int cnt  = min(32, end - k);
        int jmax = (cnt + 1) >> 1;          // uniform across warp

        #pragma unroll 8
        for (int j = 0; j < jmax; j++) {
            int e = 2 * j + half;           // this half-warp's edge slot
            int   cj = __shfl_sync(0xffffffffu, __float_as_int(cv.x), e);
            float vj = __shfl_sync(0xffffffffu, cv.y, e);
            uint2 xr = __ldg(&x[cj * U2_PER_NODE + hl]);
            float2 a = __half22float2(*(const __half2*)&xr.x);
            float2 b = __half22float2(*(const __half2*)&xr.y);
            acc.x = fmaf(vj, a.x, acc.x);
            acc.y = fmaf(vj, a.y, acc.y);
            acc.z = fmaf(vj, b.x, acc.z);
            acc.w = fmaf(vj, b.y, acc.w);
        }
    }

    // combine the two half-warps' partial sums (same dims, different edges)
    acc.x += __shfl_xor_sync(0xffffffffu, acc.x, 16);
    acc.y += __shfl_xor_sync(0xffffffffu, acc.y, 16);
    acc.z += __shfl_xor_sync(0xffffffffu, acc.z, 16);
    acc.w += __shfl_xor_sync(0xffffffffu, acc.w, 16);

    if (half == 0) {
        if (MODE == 0) {
            uint2 o;
            __half2 lo = __float22half2_rn(make_float2(acc.x, acc.y));
            __half2 hi = __float22half2_rn(make_float2(acc.z, acc.w));
            o.x = *(const unsigned int*)&lo;
            o.y = *(const unsigned int*)&hi;
            ((uint2*)g_x[dstsel])[row * U2_PER_NODE + hl] = o;
        } else {
            int fi = row * F4_PER_NODE + hl;
            float4 x0 = (row < N_USERS)
                      ? __ldg(&user4[fi])
                      : __ldg(&item4[fi - N_USERS * F4_PER_NODE]);
            uint2 r1 = __ldg(&((const uint2*)g_x[1])[row * U2_PER_NODE + hl]);
            uint2 r2 = __ldg(&((const uint2*)g_x[2])[row * U2_PER_NODE + hl]);
            float2 a1 = __half22float2(*(const __half2*)&r1.x);
            float2 b1 = __half22float2(*(const __half2*)&r1.y);
            float2 a2 = __half22float2(*(const __half2*)&r2.x);
            float2 b2 = __half22float2(*(const __half2*)&r2.y);
            float4 o;
            o.x = (x0.x + a1.x + a2.x + acc.x) * 0.25f;
            o.y = (x0.y + a1.y + a2.y + acc.y) * 0.25f;
            o.z = (x0.z + b1.x + b2.x + acc.z) * 0.25f;
            o.w = (x0.w + b1.y + b2.y + acc.w) * 0.25f;
            __stcs(&out4[fi], o);
        }
    }
}

extern "C" void kernel_launch(void* const* d_in, const int* in_sizes, int n_in,
                              void* d_out, int out_size) {
    const float2* user = (const float2*)d_in[0];
    const float2* item = (const float2*)d_in[1];
    const int*   rows  = (const int*)d_in[2];
    const int4*  rows4 = (const int4*)d_in[2];
    const int4*  cols4 = (const int4*)d_in[3];
    const float4* vals4 = (const float4*)d_in[4];
    const float4* user4 = (const float4*)d_in[0];
    const float4* item4 = (const float4*)d_in[1];
    float4* out4 = (float4*)d_out;

    const int BLK = 256;
    const int gridBuf   = (BUF_H2 + BLK - 1) / BLK;         // covers init & hist
    const int gridEdge8 = (NNZ / 8 + BLK - 1) / BLK;
    const int gridSpmm  = (N_NODES * 32 + BLK - 1) / BLK;   // warp per row

    // CSR build + x0 init
    int* d_deg = nullptr;
    cudaGetSymbolAddress((void**)&d_deg, g_deg);
    cudaMemsetAsync(d_deg, 0, N_NODES * sizeof(int));
    init_hist_kernel<<<gridBuf, BLK>>>(user, item, rows);
    scan1_kernel<<<N_SCAN_BLOCKS, SCAN_BLK>>>();
    scan23_kernel<<<N_SCAN_BLOCKS, SCAN_BLK>>>();
    scatter_kernel<<<gridEdge8, BLK>>>(rows4, cols4, vals4);

    // 3 propagation layers; layer 3 fuses the final average + fp32 output
    spmm_csr_kernel<0><<<gridSpmm, BLK>>>(0, 1, user4, item4, out4); // x1 = A@x0
    spmm_csr_kernel<0><<<gridSpmm, BLK>>>(1, 2, user4, item4, out4); // x2 = A@x1
    spmm_csr_kernel<1><<<gridSpmm, BLK>>>(2, 0, user4, item4, out4); // out=(x0+x1+x2+A@x2)/4
}

// round 17
// speedup vs baseline: 1.3432x; 1.0069x over previous
#include <cuda_runtime.h>
#include <cuda_fp16.h>

#define N_USERS 100000
#define N_ITEMS 200000
#define N_NODES (N_USERS + N_ITEMS)
#define NNZ 6400000
#define H2_PER_NODE 32                      // 64 dims = 32 half2
#define U2_PER_NODE 16                      // 64 dims = 16 uint2 (4 half each)
#define F4_PER_NODE 16                      // 64 dims = 16 float4
#define BUF_H2 (N_NODES * H2_PER_NODE)      // 9.6M half2 = 38.4 MB
#define SCAN_BLK 1024
#define N_SCAN_BLOCKS ((N_NODES + SCAN_BLK - 1) / SCAN_BLK)   // 293

// Static device scratch. g_x[0]=x0, [1]=x1, [2]=x2 (fp16). x3 never stored.
__device__ __align__(128) __half2 g_x[3][BUF_H2];   // 3 x 38.4 MB
__device__ float2  g_cv[NNZ + 1];            // packed {col_bits, val} (+1 pad)
__device__ int     g_rowptr[N_NODES + 1];
__device__ int     g_cursor[N_NODES];
__device__ int     g_deg[N_NODES];
__device__ int     g_bsum[SCAN_BLK];

// ------------- fused init + histogram (fire-and-forget atomics) -------------
__global__ void init_hist_kernel(const float2* __restrict__ user,
                                 const float2* __restrict__ item,
                                 const int* __restrict__ rows) {
    int i = blockIdx.x * blockDim.x + threadIdx.x;
    if (i < BUF_H2) {
        const int uend = N_USERS * H2_PER_NODE;
        float2 v = (i < uend) ? user[i] : item[i - uend];
        g_x[0][i] = __float22half2_rn(v);
    }
    if (i < NNZ) {
        atomicAdd(&g_deg[rows[i]], 1);
    }
}

// ------------- scan1: per-block exclusive scan, block sums to g_bsum -------------
__global__ void scan1_kernel() {
    __shared__ int s[SCAN_BLK];
    int t = threadIdx.x;
    int i = blockIdx.x * SCAN_BLK + t;
    int v = (i < N_NODES) ? g_deg[i] : 0;
    s[t] = v;
    __syncthreads();
    for (int off = 1; off < SCAN_BLK; off <<= 1) {
        int add = (t >= off) ? s[t - off] : 0;
        __syncthreads();
        s[t] += add;
        __syncthreads();
    }
    int incl = s[t];
    if (i < N_NODES) g_rowptr[i] = incl - v;
    if (t == SCAN_BLK - 1) g_bsum[blockIdx.x] = incl;
}

// ------------- scan23: each block computes its own bsum prefix + applies -------------
__global__ void scan23_kernel() {
    __shared__ int s_off;
    int bid = blockIdx.x;
    int t = threadIdx.x;
    if (t < 32) {
        int acc = 0;
        for (int j = t; j < bid; j += 32) acc += g_bsum[j];
        #pragma unroll
        for (int o = 16; o; o >>= 1) acc += __shfl_xor_sync(0xffffffffu, acc, o);
        if (t == 0) s_off = acc;
    }
    __syncthreads();
    int i = bid * SCAN_BLK + t;
    if (i < N_NODES) {
        int rp = g_rowptr[i] + s_off;
        g_rowptr[i] = rp;
        g_cursor[i] = rp;
        if (i == 0) g_rowptr[N_NODES] = NNZ;
    }
}

// ------------- scatter: 4 edges/thread, 4 independent atomic+store chains -------------
__global__ void scatter_kernel(const int4* __restrict__ rows4,
                               const int4* __restrict__ cols4,
                               const float4* __restrict__ vals4) {
    int i = blockIdx.x * blockDim.x + threadIdx.x;
    if (i >= NNZ / 4) return;
    int4   r = __ldcs(&rows4[i]);
    int4   c = __ldcs(&cols4[i]);
    float4 v = __ldcs(&vals4[i]);

    int p0 = atomicAdd(&g_cursor[r.x], 1);
    int p1 = atomicAdd(&g_cursor[r.y], 1);
    int p2 = atomicAdd(&g_cursor[r.z], 1);
    int p3 = atomicAdd(&g_cursor[r.w], 1);

    __stcs(&g_cv[p0], make_float2(__int_as_float(c.x), v.x));
    __stcs(&g_cv[p1], make_float2(__int_as_float(c.y), v.y));
    __stcs(&g_cv[p2], make_float2(__int_as_float(c.z), v.z));
    __stcs(&g_cv[p3], make_float2(__int_as_float(c.w), v.w));
}

// ---------------- CSR SpMM: warp per row, 16 lanes x uint2, 2 edges/step ------
// cv: evict_first. y store: evict_first (not re-read this layer).
// MODE-1 x1/x2 reads: evict_first (read-once). x gathers: default policy.
// MODE 0: y[row] = fp16(sum)                                (layers 1,2)
// MODE 1: out[row] = (x0_fp32 + x1 + x2 + sum) * 0.25       (layer 3, fused final)
template <int MODE>
__global__ void spmm_csr_kernel(int srcsel, int dstsel,
                                const float4* __restrict__ user4,
                                const float4* __restrict__ item4,
                                float4* __restrict__ out4) {
    int gtid = blockIdx.x * blockDim.x + threadIdx.x;
    int row = gtid >> 5;
    int lane = threadIdx.x & 31;
    if (row >= N_NODES) return;

    int half = lane >> 4;       // 0 or 1
    int hl   = lane & 15;       // lane within half-warp

    const uint2* __restrict__ x = (const uint2*)g_x[srcsel];

    int start = __ldg(&g_rowptr[row]);
    int end   = __ldg(&g_rowptr[row + 1]);

    float4 acc = make_float4(0.f, 0.f, 0.f, 0.f);

    for (int k = start; k < end; k += 32) {
        int myk = k + lane;
        // zero-fill => col 0, val 0: contributes nothing, loads stay valid
        float2 cv = (myk < end) ? __ldcs(&g_cv[myk]) : make_float2(0.f, 0.f);
        int cnt  = min(32, end - k);
        int jmax = (cnt + 1) >> 1;          // uniform across warp

        #pragma unroll 8
        for (int j = 0; j < jmax; j++) {
            int e = 2 * j + half;           // this half-warp's edge slot
            int   cj = __shfl_sync(0xffffffffu, __float_as_int(cv.x), e);
            float vj = __shfl_sync(0xffffffffu, cv.y, e);
            uint2 xr = __ldg(&x[cj * U2_PER_NODE + hl]);
            float2 a = __half22float2(*(const __half2*)&xr.x);
            float2 b = __half22float2(*(const __half2*)&xr.y);
            acc.x = fmaf(vj, a.x, acc.x);
            acc.y = fmaf(vj, a.y, acc.y);
            acc.z = fmaf(vj, b.x, acc.z);
            acc.w = fmaf(vj, b.y, acc.w);
        }
    }

    // combine the two half-warps' partial sums (same dims, different edges)
    acc.x += __shfl_xor_sync(0xffffffffu, acc.x, 16);
    acc.y += __shfl_xor_sync(0xffffffffu, acc.y, 16);
    acc.z += __shfl_xor_sync(0xffffffffu, acc.z, 16);
    acc.w += __shfl_xor_sync(0xffffffffu, acc.w, 16);

    if (half == 0) {
        if (MODE == 0) {
            uint2 o;
            __half2 lo = __float22half2_rn(make_float2(acc.x, acc.y));
            __half2 hi = __float22half2_rn(make_float2(acc.z, acc.w));
            o.x = *(const unsigned int*)&lo;
            o.y = *(const unsigned int*)&hi;
            __stcs(&((uint2*)g_x[dstsel])[row * U2_PER_NODE + hl], o);
        } else {
            int fi = row * F4_PER_NODE + hl;
            float4 x0 = (row < N_USERS)
                      ? __ldg(&user4[fi])
                      : __ldg(&item4[fi - N_USERS * F4_PER_NODE]);
            uint2 r1 = __ldcs(&((const uint2*)g_x[1])[row * U2_PER_NODE + hl]);
            uint2 r2 = __ldcs(&((const uint2*)g_x[2])[row * U2_PER_NODE + hl]);
            float2 a1 = __half22float2(*(const __half2*)&r1.x);
            float2 b1 = __half22float2(*(const __half2*)&r1.y);
            float2 a2 = __half22float2(*(const __half2*)&r2.x);
            float2 b2 = __half22float2(*(const __half2*)&r2.y);
            float4 o;
            o.x = (x0.x + a1.x + a2.x + acc.x) * 0.25f;
            o.y = (x0.y + a1.y + a2.y + acc.y) * 0.25f;
            o.z = (x0.z + b1.x + b2.x + acc.z) * 0.25f;
            o.w = (x0.w + b1.y + b2.y + acc.w) * 0.25f;
            __stcs(&out4[fi], o);
        }
    }
}

extern "C" void kernel_launch(void* const* d_in, const int* in_sizes, int n_in,
                              void* d_out, int out_size) {
    const float2* user = (const float2*)d_in[0];
    const float2* item = (const float2*)d_in[1];
    const int*   rows  = (const int*)d_in[2];
    const int4*  rows4 = (const int4*)d_in[2];
    const int4*  cols4 = (const int4*)d_in[3];
    const float4* vals4 = (const float4*)d_in[4];
    const float4* user4 = (const float4*)d_in[0];
    const float4* item4 = (const float4*)d_in[1];
    float4* out4 = (float4*)d_out;

    const int BLK = 256;
    const int gridBuf   = (BUF_H2 + BLK - 1) / BLK;         // covers init & hist
    const int gridEdge4 = (NNZ / 4 + BLK - 1) / BLK;
    const int gridSpmm  = (N_NODES * 32 + BLK - 1) / BLK;   // warp per row

    // CSR build + x0 init
    int* d_deg = nullptr;
    cudaGetSymbolAddress((void**)&d_deg, g_deg);
    cudaMemsetAsync(d_deg, 0, N_NODES * sizeof(int));
    init_hist_kernel<<<gridBuf, BLK>>>(user, item, rows);
    scan1_kernel<<<N_SCAN_BLOCKS, SCAN_BLK>>>();
    scan23_kernel<<<N_SCAN_BLOCKS, SCAN_BLK>>>();
    scatter_kernel<<<gridEdge4, BLK>>>(rows4, cols4, vals4);

    // 3 propagation layers; layer 3 fuses the final average + fp32 output
    spmm_csr_kernel<0><<<gridSpmm, BLK>>>(0, 1, user4, item4, out4); // x1 = A@x0
    spmm_csr_kernel<0><<<gridSpmm, BLK>>>(1, 2, user4, item4, out4); // x2 = A@x1
    spmm_csr_kernel<1><<<gridSpmm, BLK>>>(2, 0, user4, item4, out4); // out=(x0+x1+x2+A@x2)/4
}